// round 4
// baseline (speedup 1.0000x reference)
#include <cuda_runtime.h>
#include <math.h>

#define NN 8192
#define FIN 256
#define HD_TOT 256

// Scratch (allocation-free rule: __device__ globals)
__device__ float  g_h[NN * HD_TOT];       // 8 MB: h = x @ W, layout [n][h*64+d]
__device__ float4 g_spack[NN * 4];        // per (node, head): {s, e^s, e^{0.2s}, _}
__device__ float4 g_dpack[NN * 4];        // per (node, head): {d, e^d, e^{0.2d}, _}

// ---------------------------------------------------------------------------
// K1: g_h = x @ W   (8192x256 @ 256x256), 64x64 tiles, 4x4 micro
// ---------------------------------------------------------------------------
__global__ __launch_bounds__(256) void k1_linear(const float* __restrict__ x,
                                                 const float* __restrict__ W) {
    __shared__ float as[32][68];   // A transposed [k][m], stride 68 (16B aligned)
    __shared__ float bs[32][64];   // B [k][n]
    const int rbase = blockIdx.x * 64;
    const int cbase = blockIdx.y * 64;
    const int tid = threadIdx.x;
    const int tm = tid >> 4, tn = tid & 15;
    float acc[4][4];
#pragma unroll
    for (int u = 0; u < 4; u++)
#pragma unroll
        for (int v = 0; v < 4; v++) acc[u][v] = 0.f;

    for (int k0 = 0; k0 < FIN; k0 += 32) {
        __syncthreads();
#pragma unroll
        for (int q = 0; q < 2; q++) {
            int f = tid + 256 * q;               // 512 float4: 64 rows x 8 f4
            int row = f >> 3, c4 = (f & 7) * 4;
            float4 v = *(const float4*)&x[(rbase + row) * FIN + k0 + c4];
            as[c4 + 0][row] = v.x;
            as[c4 + 1][row] = v.y;
            as[c4 + 2][row] = v.z;
            as[c4 + 3][row] = v.w;
        }
#pragma unroll
        for (int q = 0; q < 2; q++) {
            int f = tid + 256 * q;               // 512 float4: 32 rows x 16 f4
            int row = f >> 4, c4 = (f & 15) * 4;
            *(float4*)&bs[row][c4] = *(const float4*)&W[(k0 + row) * HD_TOT + cbase + c4];
        }
        __syncthreads();
#pragma unroll
        for (int k = 0; k < 32; k++) {
            float a[4], b[4];
            *(float4*)a = *(float4*)&as[k][tm * 4];
            *(float4*)b = *(float4*)&bs[k][tn * 4];
#pragma unroll
            for (int u = 0; u < 4; u++)
#pragma unroll
                for (int v = 0; v < 4; v++) acc[u][v] = fmaf(a[u], b[v], acc[u][v]);
        }
    }
#pragma unroll
    for (int u = 0; u < 4; u++) {
        *(float4*)&g_h[(rbase + tm * 4 + u) * HD_TOT + cbase + tn * 4] =
            make_float4(acc[u][0], acc[u][1], acc[u][2], acc[u][3]);
    }
}

// ---------------------------------------------------------------------------
// K2: per-node per-head scores s,d and their exp factorizations.
// One warp per node; warp-shuffle reductions over 64 dims.
// ---------------------------------------------------------------------------
__global__ __launch_bounds__(256) void k2_scores(const float* __restrict__ a_src,
                                                 const float* __restrict__ a_dst) {
    const int n = blockIdx.x * 8 + (threadIdx.x >> 5);
    const int lane = threadIdx.x & 31;
    const float* hrow = g_h + (size_t)n * HD_TOT;
#pragma unroll
    for (int h = 0; h < 4; h++) {
        float h0 = hrow[h * 64 + lane];
        float h1 = hrow[h * 64 + 32 + lane];
        float sv = h0 * a_src[h * 64 + lane] + h1 * a_src[h * 64 + 32 + lane];
        float dv = h0 * a_dst[h * 64 + lane] + h1 * a_dst[h * 64 + 32 + lane];
#pragma unroll
        for (int off = 16; off > 0; off >>= 1) {
            sv += __shfl_xor_sync(0xffffffffu, sv, off);
            dv += __shfl_xor_sync(0xffffffffu, dv, off);
        }
        if (lane == 0) {
            g_spack[n * 4 + h] = make_float4(sv, expf(sv), expf(0.2f * sv), 0.f);
            g_dpack[n * 4 + h] = make_float4(dv, expf(dv), expf(0.2f * dv), 0.f);
        }
    }
}

// ---------------------------------------------------------------------------
// K3: masked-softmax aggregation as a GEMM with on-the-fly A.
// Block: 128 target rows x 128 cols (2 heads). BK=32 neighbor chunk.
// w[i][j][h] = adj ? (s_i+d_j > 0 ? A1_i*E1_j : A2_i*E2_j) : 0
// out[i][h*64+d] = (sum_j w * h_j[d]) / (sum_j w)
// ---------------------------------------------------------------------------
#define TI 128
#define BK 32
#define WT_STRIDE 260   // 2*128 + 4: STS.128 per-lane stride == 4 banks -> conflict-free phases
#define HB_STRIDE 132

__global__ __launch_bounds__(256, 1) void k3_aggregate(const int* __restrict__ adj,
                                                       const float* __restrict__ bias,
                                                       float* __restrict__ out) {
    extern __shared__ float smem[];
    float4* sA = (float4*)smem;                 // [128][2] {s,A1,A2,_}      : 1024 floats
    float* wT = smem + 1024;                    // [BK][h*128 + i], str 260  : 8320 floats
    float* hB = wT + BK * WT_STRIDE;            // [BK][c], str 132          : 4224 floats
    float* zs = hB + BK * HB_STRIDE;            // [128][2]                  : 256 floats

    const int ibase = blockIdx.x * TI;
    const int y = blockIdx.y;        // head pair: heads (2y, 2y+1)
    const int h0 = y * 2;
    const int cbase = y * 128;
    const int tid = threadIdx.x;
    const int lane = tid & 31, warp = tid >> 5;
    const int irow = warp * 16;

    for (int f = tid; f < TI * 2; f += 256)
        sA[f] = g_spack[(ibase + (f >> 1)) * 4 + h0 + (f & 1)];

    const int rg = tid >> 4, cg = tid & 15;
    const int r0 = rg * 8, c0 = cg * 8;
    const int hsel = (cg >= 8) ? 1 : 0;

    float acc[8][8];
#pragma unroll
    for (int u = 0; u < 8; u++)
#pragma unroll
        for (int v = 0; v < 8; v++) acc[u][v] = 0.f;
    float z0 = 0.f, z1 = 0.f;

    for (int jb = 0; jb < NN; jb += BK) {
        __syncthreads();
        // stage hB: h[jb..jb+31][cbase..cbase+127]
#pragma unroll
        for (int q = 0; q < 4; q++) {
            int f = tid + 256 * q;               // 1024 float4: 32 rows x 32 f4
            int row = f >> 5, c4 = (f & 31) * 4;
            *(float4*)&hB[row * HB_STRIDE + c4] =
                *(const float4*)&g_h[(jb + row) * HD_TOT + cbase + c4];
        }
        // compute weight tile: this thread -> j = jb+lane, i = irow..irow+15, 2 heads
        {
            const float4 de0 = g_dpack[(jb + lane) * 4 + h0];
            const float4 de1 = g_dpack[(jb + lane) * 4 + h0 + 1];
            const int* adjp = adj + (size_t)(ibase + irow) * NN + jb + lane;
            float w0b[4], w1b[4];
#pragma unroll
            for (int ii = 0; ii < 16; ii++) {
                int av = adjp[ii * NN];
                float4 sa0 = sA[(irow + ii) * 2 + 0];
                float4 sa1 = sA[(irow + ii) * 2 + 1];
                float t0 = sa0.x + de0.x;
                float t1 = sa1.x + de1.x;
                float w0 = (t0 > 0.f) ? sa0.y * de0.y : sa0.z * de0.z;
                float w1 = (t1 > 0.f) ? sa1.y * de1.y : sa1.z * de1.z;
                if (av == 0) { w0 = 0.f; w1 = 0.f; }
                w0b[ii & 3] = w0;
                w1b[ii & 3] = w1;
                if ((ii & 3) == 3) {
                    *(float4*)&wT[lane * WT_STRIDE + irow + ii - 3] =
                        make_float4(w0b[0], w0b[1], w0b[2], w0b[3]);
                    *(float4*)&wT[lane * WT_STRIDE + 128 + irow + ii - 3] =
                        make_float4(w1b[0], w1b[1], w1b[2], w1b[3]);
                }
            }
        }
        __syncthreads();
        // FMA: acc[u][v] += w[r0+u][k][hsel] * h[k][c0+v]
#pragma unroll
        for (int k = 0; k < BK; k++) {
            float a[8], b[8];
            *(float4*)&a[0] = *(float4*)&wT[k * WT_STRIDE + hsel * 128 + r0];
            *(float4*)&a[4] = *(float4*)&wT[k * WT_STRIDE + hsel * 128 + r0 + 4];
            *(float4*)&b[0] = *(float4*)&hB[k * HB_STRIDE + c0];
            *(float4*)&b[4] = *(float4*)&hB[k * HB_STRIDE + c0 + 4];
#pragma unroll
            for (int u = 0; u < 8; u++)
#pragma unroll
                for (int v = 0; v < 8; v++) acc[u][v] = fmaf(a[u], b[v], acc[u][v]);
        }
        // Z partials: thread i (tid<128) sums this chunk's weights over j
        if (tid < TI) {
            float zz0 = 0.f, zz1 = 0.f;
#pragma unroll
            for (int k = 0; k < BK; k++) {
                zz0 += wT[k * WT_STRIDE + tid];
                zz1 += wT[k * WT_STRIDE + 128 + tid];
            }
            z0 += zz0;
            z1 += zz1;
        }
    }
    __syncthreads();
    if (tid < TI) { zs[tid * 2 + 0] = z0; zs[tid * 2 + 1] = z1; }
    __syncthreads();

    float bv[8];
#pragma unroll
    for (int v = 0; v < 8; v++) bv[v] = bias[cbase + c0 + v];
#pragma unroll
    for (int u = 0; u < 8; u++) {
        float inv = 1.f / zs[(r0 + u) * 2 + hsel];
#pragma unroll
        for (int v = 0; v < 8; v++) acc[u][v] = acc[u][v] * inv + bv[v];
        *(float4*)&out[(size_t)(ibase + r0 + u) * HD_TOT + cbase + c0] =
            make_float4(acc[u][0], acc[u][1], acc[u][2], acc[u][3]);
        *(float4*)&out[(size_t)(ibase + r0 + u) * HD_TOT + cbase + c0 + 4] =
            make_float4(acc[u][4], acc[u][5], acc[u][6], acc[u][7]);
    }
}

// ---------------------------------------------------------------------------
extern "C" void kernel_launch(void* const* d_in, const int* in_sizes, int n_in,
                              void* d_out, int out_size) {
    const float* x     = (const float*)d_in[0];
    const int*   adj   = (const int*)d_in[1];
    const float* W     = (const float*)d_in[2];
    const float* a_src = (const float*)d_in[3];
    const float* a_dst = (const float*)d_in[4];
    const float* bias  = (const float*)d_in[5];
    float* out = (float*)d_out;

    (void)in_sizes; (void)n_in; (void)out_size;

    static const int k3_smem = (1024 + BK * WT_STRIDE + BK * HB_STRIDE + 256) * 4;
    cudaFuncSetAttribute(k3_aggregate, cudaFuncAttributeMaxDynamicSharedMemorySize, k3_smem);

    k1_linear<<<dim3(NN / 64, HD_TOT / 64), 256>>>(x, W);
    k2_scores<<<NN / 8, 256>>>(a_src, a_dst);
    k3_aggregate<<<dim3(NN / TI, 2), 256, k3_smem>>>(adj, bias, out);
}

// round 6
// speedup vs baseline: 2.6461x; 2.6461x over previous
#include <cuda_runtime.h>
#include <cuda_fp16.h>
#include <cstdint>
#include <math.h>

#define NN 8192
#define FIN 256
#define HD_TOT 256

// Scratch (allocation-free rule: __device__ globals)
__device__ float  g_h[NN * HD_TOT];                     // fp32 h = x @ W (for K2)
__device__ __align__(16) __half g_hh[NN * HD_TOT];      // fp16 h (MMA B operand)
__device__ float4 g_spack[NN * 4];                      // {s,  e^s,  e^{0.2s}, _}
__device__ float4 g_dpack[NN * 4];                      // {d,  e^d,  e^{0.2d}, _}

// ---------------------------------------------------------------------------
// K1: g_h / g_hh = x @ W   (8192x256 @ 256x256), 64x64 tiles, 4x4 micro
// ---------------------------------------------------------------------------
__global__ __launch_bounds__(256) void k1_linear(const float* __restrict__ x,
                                                 const float* __restrict__ W) {
    __shared__ float as[32][68];
    __shared__ float bs[32][64];
    const int rbase = blockIdx.x * 64;
    const int cbase = blockIdx.y * 64;
    const int tid = threadIdx.x;
    const int tm = tid >> 4, tn = tid & 15;
    float acc[4][4];
#pragma unroll
    for (int u = 0; u < 4; u++)
#pragma unroll
        for (int v = 0; v < 4; v++) acc[u][v] = 0.f;

    for (int k0 = 0; k0 < FIN; k0 += 32) {
        __syncthreads();
#pragma unroll
        for (int q = 0; q < 2; q++) {
            int f = tid + 256 * q;
            int row = f >> 3, c4 = (f & 7) * 4;
            float4 v = *(const float4*)&x[(rbase + row) * FIN + k0 + c4];
            as[c4 + 0][row] = v.x;
            as[c4 + 1][row] = v.y;
            as[c4 + 2][row] = v.z;
            as[c4 + 3][row] = v.w;
        }
#pragma unroll
        for (int q = 0; q < 2; q++) {
            int f = tid + 256 * q;
            int row = f >> 4, c4 = (f & 15) * 4;
            *(float4*)&bs[row][c4] = *(const float4*)&W[(k0 + row) * HD_TOT + cbase + c4];
        }
        __syncthreads();
#pragma unroll
        for (int k = 0; k < 32; k++) {
            float a[4], b[4];
            *(float4*)a = *(float4*)&as[k][tm * 4];
            *(float4*)b = *(float4*)&bs[k][tn * 4];
#pragma unroll
            for (int u = 0; u < 4; u++)
#pragma unroll
                for (int v = 0; v < 4; v++) acc[u][v] = fmaf(a[u], b[v], acc[u][v]);
        }
    }
#pragma unroll
    for (int u = 0; u < 4; u++) {
        size_t off = (size_t)(rbase + tm * 4 + u) * HD_TOT + cbase + tn * 4;
        *(float4*)&g_h[off] = make_float4(acc[u][0], acc[u][1], acc[u][2], acc[u][3]);
        __half2* hp = (__half2*)&g_hh[off];
        hp[0] = __floats2half2_rn(acc[u][0], acc[u][1]);
        hp[1] = __floats2half2_rn(acc[u][2], acc[u][3]);
    }
}

// ---------------------------------------------------------------------------
// K2: per-node per-head scores s,d and their exp factorizations.
// ---------------------------------------------------------------------------
__global__ __launch_bounds__(256) void k2_scores(const float* __restrict__ a_src,
                                                 const float* __restrict__ a_dst) {
    const int n = blockIdx.x * 8 + (threadIdx.x >> 5);
    const int lane = threadIdx.x & 31;
    const float* hrow = g_h + (size_t)n * HD_TOT;
#pragma unroll
    for (int h = 0; h < 4; h++) {
        float h0 = hrow[h * 64 + lane];
        float h1 = hrow[h * 64 + 32 + lane];
        float sv = h0 * a_src[h * 64 + lane] + h1 * a_src[h * 64 + 32 + lane];
        float dv = h0 * a_dst[h * 64 + lane] + h1 * a_dst[h * 64 + 32 + lane];
#pragma unroll
        for (int off = 16; off > 0; off >>= 1) {
            sv += __shfl_xor_sync(0xffffffffu, sv, off);
            dv += __shfl_xor_sync(0xffffffffu, dv, off);
        }
        if (lane == 0) {
            g_spack[n * 4 + h] = make_float4(sv, expf(sv), expf(0.2f * sv), 0.f);
            g_dpack[n * 4 + h] = make_float4(dv, expf(dv), expf(0.2f * dv), 0.f);
        }
    }
}

// ---------------------------------------------------------------------------
// PTX helpers (functions, not macros)
// ---------------------------------------------------------------------------
__device__ __forceinline__ void mma16816(float* c, const unsigned* a,
                                         unsigned b0, unsigned b1) {
    asm volatile("mma.sync.aligned.m16n8k16.row.col.f32.f16.f16.f32 "
                 "{%0,%1,%2,%3}, {%4,%5,%6,%7}, {%8,%9}, {%0,%1,%2,%3};"
                 : "+f"(c[0]), "+f"(c[1]), "+f"(c[2]), "+f"(c[3])
                 : "r"(a[0]), "r"(a[1]), "r"(a[2]), "r"(a[3]), "r"(b0), "r"(b1));
}

__device__ __forceinline__ void ldsm_x4_trans(unsigned& r0, unsigned& r1,
                                              unsigned& r2, unsigned& r3,
                                              unsigned addr) {
    asm volatile("ldmatrix.sync.aligned.m8n8.x4.trans.shared.b16 {%0,%1,%2,%3}, [%4];"
                 : "=r"(r0), "=r"(r1), "=r"(r2), "=r"(r3) : "r"(addr));
}

__device__ __forceinline__ void ldsm_x2_trans(unsigned& r0, unsigned& r1,
                                              unsigned addr) {
    asm volatile("ldmatrix.sync.aligned.m8n8.x2.trans.shared.b16 {%0,%1}, [%2];"
                 : "=r"(r0), "=r"(r1) : "r"(addr));
}

__device__ __forceinline__ float gat_w(float4 s, float4 d, int av) {
    float tt = s.x + d.x;
    float p = (tt > 0.f) ? s.y * d.y : s.z * d.z;
    return av ? p : 0.f;
}

// ---------------------------------------------------------------------------
// K3: tensor-core masked-softmax aggregation.
// Block: 64 target rows x 4 heads; BK=32 neighbor chunk.
// A (weights) built directly in MMA fragment registers (no SMEM for A).
// B = fp16 h staged in SMEM; ninth n-tile of ones accumulates Z = sum_j w.
// ---------------------------------------------------------------------------
#define HS_PITCH 264   // halfs per row: 256 data + 8 ones-tile

__global__ __launch_bounds__(256, 1) void k3_mma(const int* __restrict__ adj,
                                                 const float* __restrict__ bias,
                                                 float* __restrict__ out) {
    __shared__ __align__(16) __half hs[32 * HS_PITCH];   // B tile: [k=32][256 cols + ones]
    __shared__ __align__(16) float4 dsm[32 * 5];         // d-pack, padded stride 5

    const int tid = threadIdx.x;
    const int lane = tid & 31, warp = tid >> 5;
    const int wr = warp & 3;              // row group: rows wr*16 .. +15
    const int h0 = (warp >> 2) * 2;       // head pair
    const int R = wr * 16;
    const int g = lane >> 2, t = lane & 3;
    const int ibase = blockIdx.x * 64;
    const int row0 = ibase + R + g;       // this thread's rows: row0, row0+8

    // hoisted src-side factors for 2 rows x 2 heads
    float4 sA00 = g_spack[row0 * 4 + h0];
    float4 sA01 = g_spack[row0 * 4 + h0 + 1];
    float4 sA10 = g_spack[(row0 + 8) * 4 + h0];
    float4 sA11 = g_spack[(row0 + 8) * 4 + h0 + 1];

    // ones tile (cols 256..263): col 256 = 1, rest 0. Written once.
    if (tid < 32) {
        hs[tid * HS_PITCH + 256] = __float2half(1.0f);
#pragma unroll
        for (int c = 1; c < 8; c++) hs[tid * HS_PITCH + 256 + c] = __float2half(0.0f);
    }

    float acc[2][9][4];
#pragma unroll
    for (int h2 = 0; h2 < 2; h2++)
#pragma unroll
        for (int nt = 0; nt < 9; nt++)
#pragma unroll
            for (int r = 0; r < 4; r++) acc[h2][nt][r] = 0.f;

    const unsigned hs_u = (unsigned)__cvta_generic_to_shared(hs);

    for (int jb = 0; jb < NN; jb += 32) {
        __syncthreads();
        // stage B: h fp16 rows jb..jb+31, cols 0..255
#pragma unroll
        for (int q = 0; q < 4; q++) {
            int f = tid + 256 * q;
            int r = f >> 5, c8 = (f & 31) * 8;
            *(int4*)&hs[r * HS_PITCH + c8] =
                *(const int4*)&g_hh[(size_t)(jb + r) * HD_TOT + c8];
        }
        // stage dst-side factors for this j-chunk
        if (tid < 128) dsm[(tid >> 2) * 5 + (tid & 3)] = g_dpack[jb * 4 + tid];
        __syncthreads();

        // ---- build A fragments in registers ----
        unsigned afr[2][2][4];   // [head2][kstep][a0..a3]
#pragma unroll
        for (int ks = 0; ks < 2; ks++) {
#pragma unroll
            for (int jp = 0; jp < 2; jp++) {
                const int j0 = ks * 16 + jp * 8 + t * 2;   // local j (even)
                const int2 av0 = *(const int2*)(adj + (size_t)row0 * NN + jb + j0);
                const int2 av1 = *(const int2*)(adj + (size_t)(row0 + 8) * NN + jb + j0);
                const float4 dA = dsm[j0 * 5 + h0];
                const float4 dB = dsm[(j0 + 1) * 5 + h0];
                const float4 dC = dsm[j0 * 5 + h0 + 1];
                const float4 dD = dsm[(j0 + 1) * 5 + h0 + 1];
                {
                    __half2 lo = __floats2half2_rn(gat_w(sA00, dA, av0.x),
                                                   gat_w(sA00, dB, av0.y));
                    __half2 hi = __floats2half2_rn(gat_w(sA10, dA, av1.x),
                                                   gat_w(sA10, dB, av1.y));
                    afr[0][ks][jp * 2 + 0] = *(unsigned*)&lo;
                    afr[0][ks][jp * 2 + 1] = *(unsigned*)&hi;
                }
                {
                    __half2 lo = __floats2half2_rn(gat_w(sA01, dC, av0.x),
                                                   gat_w(sA01, dD, av0.y));
                    __half2 hi = __floats2half2_rn(gat_w(sA11, dC, av1.x),
                                                   gat_w(sA11, dD, av1.y));
                    afr[1][ks][jp * 2 + 0] = *(unsigned*)&lo;
                    afr[1][ks][jp * 2 + 1] = *(unsigned*)&hi;
                }
            }
        }

        // ---- B loads + MMA ----
#pragma unroll
        for (int ks = 0; ks < 2; ks++) {
            const int kk = ks * 16;
            const unsigned rowaddr = hs_u + ((kk + (lane & 15)) * HS_PITCH) * 2;
#pragma unroll
            for (int h2 = 0; h2 < 2; h2++) {
                const int cb = (h0 + h2) * 64;
#pragma unroll
                for (int ntp = 0; ntp < 4; ntp++) {
                    unsigned b0, b1, b2, b3;
                    unsigned baddr = rowaddr + (cb + ntp * 16 + (lane >> 4) * 8) * 2;
                    ldsm_x4_trans(b0, b1, b2, b3, baddr);
                    mma16816(acc[h2][ntp * 2 + 0], afr[h2][ks], b0, b1);
                    mma16816(acc[h2][ntp * 2 + 1], afr[h2][ks], b2, b3);
                }
            }
            // ones tile -> Z accumulation
            unsigned o0, o1;
            ldsm_x2_trans(o0, o1, rowaddr + 256 * 2);
            mma16816(acc[0][8], afr[0][ks], o0, o1);
            mma16816(acc[1][8], afr[1][ks], o0, o1);
        }
    }

    // ---- epilogue: normalize by Z (col 0 of ones-accumulator), add bias ----
#pragma unroll
    for (int h2 = 0; h2 < 2; h2++) {
        float Z0 = __shfl_sync(0xffffffffu, acc[h2][8][0], lane & 0x1c);
        float Z1 = __shfl_sync(0xffffffffu, acc[h2][8][2], lane & 0x1c);
        float i0 = 1.f / Z0;
        float i1 = 1.f / Z1;
#pragma unroll
        for (int nt = 0; nt < 8; nt++) {
            int col = (h0 + h2) * 64 + nt * 8 + t * 2;
            float b0v = bias[col], b1v = bias[col + 1];
            float2 v0 = make_float2(acc[h2][nt][0] * i0 + b0v, acc[h2][nt][1] * i0 + b1v);
            float2 v1 = make_float2(acc[h2][nt][2] * i1 + b0v, acc[h2][nt][3] * i1 + b1v);
            *(float2*)&out[(size_t)row0 * HD_TOT + col] = v0;
            *(float2*)&out[(size_t)(row0 + 8) * HD_TOT + col] = v1;
        }
    }
}

// ---------------------------------------------------------------------------
extern "C" void kernel_launch(void* const* d_in, const int* in_sizes, int n_in,
                              void* d_out, int out_size) {
    const float* x     = (const float*)d_in[0];
    const int*   adj   = (const int*)d_in[1];
    const float* W     = (const float*)d_in[2];
    const float* a_src = (const float*)d_in[3];
    const float* a_dst = (const float*)d_in[4];
    const float* bias  = (const float*)d_in[5];
    float* out = (float*)d_out;

    (void)in_sizes; (void)n_in; (void)out_size;

    k1_linear<<<dim3(NN / 64, HD_TOT / 64), 256>>>(x, W);
    k2_scores<<<NN / 8, 256>>>(a_src, a_dst);
    k3_mma<<<NN / 64, 256>>>(adj, bias, out);
}